// round 8
// baseline (speedup 1.0000x reference)
#include <cuda_runtime.h>

typedef unsigned long long u64;

#define LRSLOPE 0.01f

__device__ __forceinline__ u64 pk2(float lo, float hi) {
    u64 r; asm("mov.b64 %0, {%1, %2};" : "=l"(r) : "f"(lo), "f"(hi)); return r;
}
__device__ __forceinline__ void upk2(u64 v, float& lo, float& hi) {
    asm("mov.b64 {%0, %1}, %2;" : "=f"(lo), "=f"(hi) : "l"(v));
}
// Packed f32x2 FMA (sm_100+): r = a*b + c on both 32-bit halves.
__device__ __forceinline__ u64 ffma2(u64 a, u64 b, u64 c) {
    u64 r; asm("fma.rn.f32x2 %0, %1, %2, %3;" : "=l"(r) : "l"(a), "l"(b), "l"(c)); return r;
}
// leaky_relu(x) = max(x, slope*x)  (valid for 0<slope<1)
__device__ __forceinline__ u64 lrelu2(u64 v) {
    float lo, hi; upk2(v, lo, hi);
    lo = fmaxf(lo, LRSLOPE * lo);
    hi = fmaxf(hi, LRSLOPE * hi);
    return pk2(lo, hi);
}

struct Params {
    const float* W[10];   // 0..4 = ws_logs, 5..9 = ws_b   (each 8x8, row-major [out][in])
    const float* B[10];   // 0..4 = bs_logs, 5..9 = bs_b   (each 8)
};

// Run the 5-layer MLP (matrices m..m+4) on two packed row-pairs at once.
// sW layout: sW[(mat*8 + k)*8 + j] = duplicated pair of W[mat][j][k]  (k-major / transposed)
// sB layout: sB[mat*8 + j] = duplicated pair of B[mat][j]
__device__ __forceinline__ void mlp_pair2(const u64* __restrict__ sW,
                                          const u64* __restrict__ sB, int m,
                                          const u64 in0[8], const u64 in1[8],
                                          u64 out0[8], u64 out1[8]) {
    u64 c0[8], c1[8];
#pragma unroll
    for (int j = 0; j < 8; j++) { c0[j] = in0[j]; c1[j] = in1[j]; }
#pragma unroll
    for (int l = 0; l < 5; l++) {
        const u64* w  = sW + (m + l) * 64;
        const u64* bs = sB + (m + l) * 8;
        u64 a0[8], a1[8];
#pragma unroll
        for (int j = 0; j < 8; j++) { u64 bv = bs[j]; a0[j] = bv; a1[j] = bv; }
#pragma unroll
        for (int k = 0; k < 8; k++) {
            u64 x0 = c0[k], x1 = c1[k];
#pragma unroll
            for (int j = 0; j < 8; j++) {
                u64 wv = w[k * 8 + j];
                a0[j] = ffma2(wv, x0, a0[j]);   // 16 independent acc chains -> ILP
                a1[j] = ffma2(wv, x1, a1[j]);
            }
        }
        if (l < 4) {
#pragma unroll
            for (int j = 0; j < 8; j++) { c0[j] = lrelu2(a0[j]); c1[j] = lrelu2(a1[j]); }
        } else {
#pragma unroll
            for (int j = 0; j < 8; j++) { out0[j] = a0[j]; out1[j] = a1[j]; }
        }
    }
}

__global__ void __launch_bounds__(256)
affine_coupling_kernel(const float4* __restrict__ z4, float4* __restrict__ out4,
                       int batch, Params P) {
    __shared__ u64 sW[640];   // 10 mats * 64, transposed + duplicated
    __shared__ u64 sB[80];    // 10 mats * 8, duplicated

    for (int i = threadIdx.x; i < 640; i += blockDim.x) {
        int mm = i >> 6, r = i & 63, k = r >> 3, j = r & 7;
        float v = P.W[mm][j * 8 + k];
        sW[i] = pk2(v, v);
    }
    for (int i = threadIdx.x; i < 80; i += blockDim.x) {
        float v = P.B[i >> 3][i & 7];
        sB[i] = pk2(v, v);
    }
    __syncthreads();

    const int t = blockIdx.x * blockDim.x + threadIdx.x;
    const int q = batch >> 2;

    if (t < q) {
        const int r0 = t, r1 = t + q, r2 = t + 2 * q, r3 = t + 3 * q;

        // Load 4 rows (each row = 4 float4, lane-stride 64B -> coalesceable)
        float4 A0 = z4[r0 * 4 + 0], A1 = z4[r0 * 4 + 1], A2 = z4[r0 * 4 + 2], A3 = z4[r0 * 4 + 3];
        float4 B0 = z4[r1 * 4 + 0], B1 = z4[r1 * 4 + 1], B2 = z4[r1 * 4 + 2], B3 = z4[r1 * 4 + 3];
        float4 C0 = z4[r2 * 4 + 0], C1 = z4[r2 * 4 + 1], C2 = z4[r2 * 4 + 2], C3 = z4[r2 * 4 + 3];
        float4 D0 = z4[r3 * 4 + 0], D1 = z4[r3 * 4 + 1], D2 = z4[r3 * 4 + 2], D3 = z4[r3 * 4 + 3];

        // pair0 = (r0, r1), pair1 = (r2, r3); lane .x = first row, .y = second row
        u64 zl0[8], zr0[8], zl1[8], zr1[8];
        zl0[0] = pk2(A0.x, B0.x); zl0[1] = pk2(A0.y, B0.y); zl0[2] = pk2(A0.z, B0.z); zl0[3] = pk2(A0.w, B0.w);
        zl0[4] = pk2(A1.x, B1.x); zl0[5] = pk2(A1.y, B1.y); zl0[6] = pk2(A1.z, B1.z); zl0[7] = pk2(A1.w, B1.w);
        zr0[0] = pk2(A2.x, B2.x); zr0[1] = pk2(A2.y, B2.y); zr0[2] = pk2(A2.z, B2.z); zr0[3] = pk2(A2.w, B2.w);
        zr0[4] = pk2(A3.x, B3.x); zr0[5] = pk2(A3.y, B3.y); zr0[6] = pk2(A3.z, B3.z); zr0[7] = pk2(A3.w, B3.w);
        zl1[0] = pk2(C0.x, D0.x); zl1[1] = pk2(C0.y, D0.y); zl1[2] = pk2(C0.z, D0.z); zl1[3] = pk2(C0.w, D0.w);
        zl1[4] = pk2(C1.x, D1.x); zl1[5] = pk2(C1.y, D1.y); zl1[6] = pk2(C1.z, D1.z); zl1[7] = pk2(C1.w, D1.w);
        zr1[0] = pk2(C2.x, D2.x); zr1[1] = pk2(C2.y, D2.y); zr1[2] = pk2(C2.z, D2.z); zr1[3] = pk2(C2.w, D2.w);
        zr1[4] = pk2(C3.x, D3.x); zr1[5] = pk2(C3.y, D3.y); zr1[6] = pk2(C3.z, D3.z); zr1[7] = pk2(C3.w, D3.w);

        u64 ls0[8], ls1[8], bb0[8], bb1[8];
        mlp_pair2(sW, sB, 0, zl0, zl1, ls0, ls1);   // log_s
        mlp_pair2(sW, sB, 5, zl0, zl1, bb0, bb1);   // b

        u64 yr0[8], yr1[8];
#pragma unroll
        for (int j = 0; j < 8; j++) {
            float a, b;
            upk2(ls0[j], a, b);
            yr0[j] = ffma2(pk2(__expf(a), __expf(b)), zr0[j], bb0[j]);
            upk2(ls1[j], a, b);
            yr1[j] = ffma2(pk2(__expf(a), __expf(b)), zr1[j], bb1[j]);
        }

        // Stores: out row = [zl | yr]
        float la[8], lb[8], ya[8], yb[8];
#pragma unroll
        for (int j = 0; j < 8; j++) { upk2(zl0[j], la[j], lb[j]); upk2(yr0[j], ya[j], yb[j]); }
        out4[r0 * 4 + 0] = make_float4(la[0], la[1], la[2], la[3]);
        out4[r0 * 4 + 1] = make_float4(la[4], la[5], la[6], la[7]);
        out4[r0 * 4 + 2] = make_float4(ya[0], ya[1], ya[2], ya[3]);
        out4[r0 * 4 + 3] = make_float4(ya[4], ya[5], ya[6], ya[7]);
        out4[r1 * 4 + 0] = make_float4(lb[0], lb[1], lb[2], lb[3]);
        out4[r1 * 4 + 1] = make_float4(lb[4], lb[5], lb[6], lb[7]);
        out4[r1 * 4 + 2] = make_float4(yb[0], yb[1], yb[2], yb[3]);
        out4[r1 * 4 + 3] = make_float4(yb[4], yb[5], yb[6], yb[7]);
#pragma unroll
        for (int j = 0; j < 8; j++) { upk2(zl1[j], la[j], lb[j]); upk2(yr1[j], ya[j], yb[j]); }
        out4[r2 * 4 + 0] = make_float4(la[0], la[1], la[2], la[3]);
        out4[r2 * 4 + 1] = make_float4(la[4], la[5], la[6], la[7]);
        out4[r2 * 4 + 2] = make_float4(ya[0], ya[1], ya[2], ya[3]);
        out4[r2 * 4 + 3] = make_float4(ya[4], ya[5], ya[6], ya[7]);
        out4[r3 * 4 + 0] = make_float4(lb[0], lb[1], lb[2], lb[3]);
        out4[r3 * 4 + 1] = make_float4(lb[4], lb[5], lb[6], lb[7]);
        out4[r3 * 4 + 2] = make_float4(yb[0], yb[1], yb[2], yb[3]);
        out4[r3 * 4 + 3] = make_float4(yb[4], yb[5], yb[6], yb[7]);
    }

    // Tail rows (batch % 4 != 0): at most 3 rows, scalar-ish path.
    const int tail_start = q << 2;
    if (t < batch - tail_start) {
        const int r = tail_start + t;
        const float* zrow = reinterpret_cast<const float*>(z4) + (size_t)r * 16;
        u64 in[8], zr[8];
#pragma unroll
        for (int j = 0; j < 8; j++) { in[j] = pk2(zrow[j], zrow[j]); zr[j] = pk2(zrow[8 + j], zrow[8 + j]); }
        u64 ls[8], bb[8], dmy0[8], dmy1[8];
        mlp_pair2(sW, sB, 0, in, in, ls, dmy0);
        mlp_pair2(sW, sB, 5, in, in, bb, dmy1);
        float* orow = reinterpret_cast<float*>(out4) + (size_t)r * 16;
#pragma unroll
        for (int j = 0; j < 8; j++) {
            float a, dummy, bv, zv;
            upk2(ls[j], a, dummy);
            upk2(bb[j], bv, dummy);
            upk2(zr[j], zv, dummy);
            orow[j] = zrow[j];
            orow[8 + j] = __expf(a) * zv + bv;
        }
    }
}

extern "C" void kernel_launch(void* const* d_in, const int* in_sizes, int n_in,
                              void* d_out, int out_size) {
    // ---- Robust input parsing ----
    // The lists (ws_logs, bs_logs, ws_b, bs_b) may arrive either as 20 separate
    // tensors (sizes 64/8) or as 4 stacked tensors (sizes 320/40); z is the one
    // huge tensor. Parse by size signature so BOTH layouts (and any z position)
    // work, and never index d_in beyond n_in.
    int zi = 0;
    for (int i = 1; i < n_in; i++)
        if (in_sizes[i] > in_sizes[zi]) zi = i;
    const float* z = (const float*)d_in[zi];
    int batch = in_sizes[zi] / 16;

    Params P;
    const float* wlist[10]; int wn = 0;   // order encountered: ws_logs then ws_b
    const float* blist[10]; int bn = 0;   // order encountered: bs_logs then bs_b
    for (int i = 0; i < n_in; i++) {
        if (i == zi) continue;
        const float* p = (const float*)d_in[i];
        int sz = in_sizes[i];
        if (sz == 320) { for (int m = 0; m < 5 && wn < 10; m++) wlist[wn++] = p + m * 64; }
        else if (sz == 64) { if (wn < 10) wlist[wn++] = p; }
        else if (sz == 40) { for (int m = 0; m < 5 && bn < 10; m++) blist[bn++] = p + m * 8; }
        else if (sz == 8)  { if (bn < 10) blist[bn++] = p; }
    }
    for (int i = 0; i < 10; i++) {
        P.W[i] = wlist[i < 10 ? i : 0];   // 0..4 ws_logs, 5..9 ws_b
        P.B[i] = blist[i < 10 ? i : 0];   // 0..4 bs_logs, 5..9 bs_b
    }

    int q = batch >> 2;
    int tail = batch - (q << 2);
    int work = q > tail ? q : tail;
    if (work < 1) work = 1;
    int threads = 256;
    int blocks = (work + threads - 1) / threads;
    affine_coupling_kernel<<<blocks, threads>>>((const float4*)z, (float4*)d_out, batch, P);
}

// round 9
// speedup vs baseline: 1.3242x; 1.3242x over previous
#include <cuda_runtime.h>

typedef unsigned long long u64;

#define LRSLOPE 0.01f

__device__ __forceinline__ u64 pk2(float lo, float hi) {
    u64 r; asm("mov.b64 %0, {%1, %2};" : "=l"(r) : "f"(lo), "f"(hi)); return r;
}
__device__ __forceinline__ void upk2(u64 v, float& lo, float& hi) {
    asm("mov.b64 {%0, %1}, %2;" : "=f"(lo), "=f"(hi) : "l"(v));
}
// Packed f32x2 FMA (sm_100+): r = a*b + c on both 32-bit halves.
__device__ __forceinline__ u64 ffma2(u64 a, u64 b, u64 c) {
    u64 r; asm("fma.rn.f32x2 %0, %1, %2, %3;" : "=l"(r) : "l"(a), "l"(b), "l"(c)); return r;
}
// leaky_relu(x) = max(x, slope*x): FMUL (fma pipe) + FMNMX (alu pipe)
__device__ __forceinline__ u64 lrelu2(u64 v) {
    float lo, hi; upk2(v, lo, hi);
    lo = fmaxf(lo, LRSLOPE * lo);
    hi = fmaxf(hi, LRSLOPE * hi);
    return pk2(lo, hi);
}

struct Params {
    const float* W[10];   // 0..4 = ws_logs, 5..9 = ws_b   (each 8x8, row-major [out][in])
    const float* B[10];   // 0..4 = bs_logs, 5..9 = bs_b   (each 8)
};

// 5-layer MLP (matrices m..m+4) on two packed row-pairs.
// sW layout: sW[(mat*8 + k)*8 + j] = duplicated pair of W[mat][j][k] (k-major),
// 16B-aligned so consecutive j can be fetched as one LDS.128 (ulonglong2).
// sB layout: sB[mat*8 + j] = duplicated pair of B[mat][j].
__device__ __forceinline__ void mlp_pair2(const u64* __restrict__ sW,
                                          const u64* __restrict__ sB, int m,
                                          const u64 in0[8], const u64 in1[8],
                                          u64 out0[8], u64 out1[8]) {
    u64 c0[8], c1[8];
#pragma unroll
    for (int j = 0; j < 8; j++) { c0[j] = in0[j]; c1[j] = in1[j]; }
#pragma unroll
    for (int l = 0; l < 5; l++) {
        const ulonglong2* w2 = reinterpret_cast<const ulonglong2*>(sW + (m + l) * 64);
        const ulonglong2* b2 = reinterpret_cast<const ulonglong2*>(sB + (m + l) * 8);
        u64 a0[8], a1[8];
#pragma unroll
        for (int j2 = 0; j2 < 4; j2++) {
            ulonglong2 bv = b2[j2];                       // LDS.128, broadcast
            a0[2*j2] = bv.x; a0[2*j2+1] = bv.y;
            a1[2*j2] = bv.x; a1[2*j2+1] = bv.y;
        }
#pragma unroll
        for (int k = 0; k < 8; k++) {
            u64 x0 = c0[k], x1 = c1[k];
#pragma unroll
            for (int j2 = 0; j2 < 4; j2++) {
                ulonglong2 wv = w2[k * 4 + j2];           // LDS.128: 2 weight pairs
                a0[2*j2]   = ffma2(wv.x, x0, a0[2*j2]);   // 16 independent chains
                a1[2*j2]   = ffma2(wv.x, x1, a1[2*j2]);
                a0[2*j2+1] = ffma2(wv.y, x0, a0[2*j2+1]);
                a1[2*j2+1] = ffma2(wv.y, x1, a1[2*j2+1]);
            }
        }
        if (l < 4) {
#pragma unroll
            for (int j = 0; j < 8; j++) { c0[j] = lrelu2(a0[j]); c1[j] = lrelu2(a1[j]); }
        } else {
#pragma unroll
            for (int j = 0; j < 8; j++) { out0[j] = a0[j]; out1[j] = a1[j]; }
        }
    }
}

__global__ void __launch_bounds__(256, 2)
affine_coupling_kernel(const float4* __restrict__ z4, float4* __restrict__ out4,
                       int batch, Params P) {
    __shared__ __align__(16) u64 sW[640];   // 10 mats * 64, transposed + duplicated
    __shared__ __align__(16) u64 sB[80];    // 10 mats * 8, duplicated

    for (int i = threadIdx.x; i < 640; i += blockDim.x) {
        int mm = i >> 6, r = i & 63, k = r >> 3, j = r & 7;
        float v = P.W[mm][j * 8 + k];
        sW[i] = pk2(v, v);
    }
    for (int i = threadIdx.x; i < 80; i += blockDim.x) {
        float v = P.B[i >> 3][i & 7];
        sB[i] = pk2(v, v);
    }
    __syncthreads();

    const int t = blockIdx.x * blockDim.x + threadIdx.x;
    const int q = batch >> 2;

    if (t < q) {
        const int r0 = t, r1 = t + q, r2 = t + 2 * q, r3 = t + 3 * q;

        // ---- Phase 1: load ONLY the zl halves (32B sectors; no wasted DRAM) ----
        float4 A0 = z4[r0 * 4 + 0], A1 = z4[r0 * 4 + 1];
        float4 B0 = z4[r1 * 4 + 0], B1 = z4[r1 * 4 + 1];
        float4 C0 = z4[r2 * 4 + 0], C1 = z4[r2 * 4 + 1];
        float4 D0 = z4[r3 * 4 + 0], D1 = z4[r3 * 4 + 1];

        // Output left half is a pure copy of zl -> store NOW, freeing the regs.
        out4[r0 * 4 + 0] = A0; out4[r0 * 4 + 1] = A1;
        out4[r1 * 4 + 0] = B0; out4[r1 * 4 + 1] = B1;
        out4[r2 * 4 + 0] = C0; out4[r2 * 4 + 1] = C1;
        out4[r3 * 4 + 0] = D0; out4[r3 * 4 + 1] = D1;

        // pair0 = (r0, r1), pair1 = (r2, r3); lane .x = first row, .y = second row
        u64 zl0[8], zl1[8];
        zl0[0] = pk2(A0.x, B0.x); zl0[1] = pk2(A0.y, B0.y); zl0[2] = pk2(A0.z, B0.z); zl0[3] = pk2(A0.w, B0.w);
        zl0[4] = pk2(A1.x, B1.x); zl0[5] = pk2(A1.y, B1.y); zl0[6] = pk2(A1.z, B1.z); zl0[7] = pk2(A1.w, B1.w);
        zl1[0] = pk2(C0.x, D0.x); zl1[1] = pk2(C0.y, D0.y); zl1[2] = pk2(C0.z, D0.z); zl1[3] = pk2(C0.w, D0.w);
        zl1[4] = pk2(C1.x, D1.x); zl1[5] = pk2(C1.y, D1.y); zl1[6] = pk2(C1.z, D1.z); zl1[7] = pk2(C1.w, D1.w);

        // ---- Phase 2: the two MLPs (zr NOT live here -> fits 2 CTAs/SM) ----
        u64 ls0[8], ls1[8], bb0[8], bb1[8];
        mlp_pair2(sW, sB, 0, zl0, zl1, ls0, ls1);   // log_s
        mlp_pair2(sW, sB, 5, zl0, zl1, bb0, bb1);   // b

        // ---- Phase 3: late-load zr halves, fuse exp*zr+b, store right half ----
        {
            float4 A2 = z4[r0 * 4 + 2], A3 = z4[r0 * 4 + 3];
            float4 B2 = z4[r1 * 4 + 2], B3 = z4[r1 * 4 + 3];
            u64 zr[8];
            zr[0] = pk2(A2.x, B2.x); zr[1] = pk2(A2.y, B2.y); zr[2] = pk2(A2.z, B2.z); zr[3] = pk2(A2.w, B2.w);
            zr[4] = pk2(A3.x, B3.x); zr[5] = pk2(A3.y, B3.y); zr[6] = pk2(A3.z, B3.z); zr[7] = pk2(A3.w, B3.w);
            float ya[8], yb[8];
#pragma unroll
            for (int j = 0; j < 8; j++) {
                float a, b;
                upk2(ls0[j], a, b);
                u64 y = ffma2(pk2(__expf(a), __expf(b)), zr[j], bb0[j]);
                upk2(y, ya[j], yb[j]);
            }
            out4[r0 * 4 + 2] = make_float4(ya[0], ya[1], ya[2], ya[3]);
            out4[r0 * 4 + 3] = make_float4(ya[4], ya[5], ya[6], ya[7]);
            out4[r1 * 4 + 2] = make_float4(yb[0], yb[1], yb[2], yb[3]);
            out4[r1 * 4 + 3] = make_float4(yb[4], yb[5], yb[6], yb[7]);
        }
        {
            float4 C2 = z4[r2 * 4 + 2], C3 = z4[r2 * 4 + 3];
            float4 D2 = z4[r3 * 4 + 2], D3 = z4[r3 * 4 + 3];
            u64 zr[8];
            zr[0] = pk2(C2.x, D2.x); zr[1] = pk2(C2.y, D2.y); zr[2] = pk2(C2.z, D2.z); zr[3] = pk2(C2.w, D2.w);
            zr[4] = pk2(C3.x, D3.x); zr[5] = pk2(C3.y, D3.y); zr[6] = pk2(C3.z, D3.z); zr[7] = pk2(C3.w, D3.w);
            float ya[8], yb[8];
#pragma unroll
            for (int j = 0; j < 8; j++) {
                float a, b;
                upk2(ls1[j], a, b);
                u64 y = ffma2(pk2(__expf(a), __expf(b)), zr[j], bb1[j]);
                upk2(y, ya[j], yb[j]);
            }
            out4[r2 * 4 + 2] = make_float4(ya[0], ya[1], ya[2], ya[3]);
            out4[r2 * 4 + 3] = make_float4(ya[4], ya[5], ya[6], ya[7]);
            out4[r3 * 4 + 2] = make_float4(yb[0], yb[1], yb[2], yb[3]);
            out4[r3 * 4 + 3] = make_float4(yb[4], yb[5], yb[6], yb[7]);
        }
    }

    // Tail rows (batch % 4 != 0): at most 3 rows, scalar-ish path.
    const int tail_start = q << 2;
    if (t < batch - tail_start) {
        const int r = tail_start + t;
        const float* zrow = reinterpret_cast<const float*>(z4) + (size_t)r * 16;
        u64 in[8], zr[8];
#pragma unroll
        for (int j = 0; j < 8; j++) { in[j] = pk2(zrow[j], zrow[j]); zr[j] = pk2(zrow[8 + j], zrow[8 + j]); }
        u64 ls[8], bb[8], dmy0[8], dmy1[8];
        mlp_pair2(sW, sB, 0, in, in, ls, dmy0);
        mlp_pair2(sW, sB, 5, in, in, bb, dmy1);
        float* orow = reinterpret_cast<float*>(out4) + (size_t)r * 16;
#pragma unroll
        for (int j = 0; j < 8; j++) {
            float a, dummy, bv, zv;
            upk2(ls[j], a, dummy);
            upk2(bb[j], bv, dummy);
            upk2(zr[j], zv, dummy);
            orow[j] = zrow[j];
            orow[8 + j] = __expf(a) * zv + bv;
        }
    }
}

extern "C" void kernel_launch(void* const* d_in, const int* in_sizes, int n_in,
                              void* d_out, int out_size) {
    // ---- Robust input parsing (by size signature; works for both stacked
    // (320/40) and per-matrix (64/8) flattenings; z = largest input). ----
    int zi = 0;
    for (int i = 1; i < n_in; i++)
        if (in_sizes[i] > in_sizes[zi]) zi = i;
    const float* z = (const float*)d_in[zi];
    int batch = in_sizes[zi] / 16;

    Params P;
    const float* wlist[10]; int wn = 0;   // order encountered: ws_logs then ws_b
    const float* blist[10]; int bn = 0;   // order encountered: bs_logs then bs_b
    for (int i = 0; i < n_in; i++) {
        if (i == zi) continue;
        const float* p = (const float*)d_in[i];
        int sz = in_sizes[i];
        if (sz == 320) { for (int m = 0; m < 5 && wn < 10; m++) wlist[wn++] = p + m * 64; }
        else if (sz == 64) { if (wn < 10) wlist[wn++] = p; }
        else if (sz == 40) { for (int m = 0; m < 5 && bn < 10; m++) blist[bn++] = p + m * 8; }
        else if (sz == 8)  { if (bn < 10) blist[bn++] = p; }
    }
    for (int i = 0; i < 10; i++) { P.W[i] = wlist[i]; P.B[i] = blist[i]; }

    int q = batch >> 2;
    int tail = batch - (q << 2);
    int work = q > tail ? q : tail;
    if (work < 1) work = 1;
    int threads = 256;
    int blocks = (work + threads - 1) / threads;
    affine_coupling_kernel<<<blocks, threads>>>((const float4*)z, (float4*)d_out, batch, P);
}

// round 12
// speedup vs baseline: 1.6350x; 1.2347x over previous
#include <cuda_runtime.h>

typedef unsigned long long u64;

#define LRSLOPE 0.01f

__device__ __forceinline__ u64 pk2(float lo, float hi) {
    u64 r; asm("mov.b64 %0, {%1, %2};" : "=l"(r) : "f"(lo), "f"(hi)); return r;
}
__device__ __forceinline__ void upk2(u64 v, float& lo, float& hi) {
    asm("mov.b64 {%0, %1}, %2;" : "=f"(lo), "=f"(hi) : "l"(v));
}
// duplicate one float into both halves of a packed f32x2 register
__device__ __forceinline__ u64 pkdup(float x) {
    u64 r; asm("mov.b64 %0, {%1, %1};" : "=l"(r) : "f"(x)); return r;
}
// Packed f32x2 FMA (sm_100+): r = a*b + c on both 32-bit halves.
__device__ __forceinline__ u64 ffma2(u64 a, u64 b, u64 c) {
    u64 r; asm("fma.rn.f32x2 %0, %1, %2, %3;" : "=l"(r) : "l"(a), "l"(b), "l"(c)); return r;
}

struct Params {
    const float* W[10];   // 0..4 = ws_logs, 5..9 = ws_b   (each 8x8, row-major [out][in])
    const float* B[10];   // 0..4 = bs_logs, 5..9 = bs_b   (each 8)
};

// smem weight layout (j-packed, NON-duplicated):
//   sW[(mat*8 + k)*4 + j2] = pk2(W[mat][2*j2][k], W[mat][2*j2+1][k])
//   sB[mat*4 + j2]         = pk2(B[mat][2*j2],   B[mat][2*j2+1])
// One layer on 4 independent rows; acc a[r][j2] packs outputs (2*j2, 2*j2+1).
// Bias is the k=0 FFMA2 addend -> no accumulator init instructions.
__device__ __forceinline__ void layer4(const u64* __restrict__ w, const u64* __restrict__ b,
                                       const float cf[4][8], u64 a[4][4]) {
    const ulonglong2* w2 = reinterpret_cast<const ulonglong2*>(w);
    const ulonglong2* b2 = reinterpret_cast<const ulonglong2*>(b);
    ulonglong2 bA = b2[0], bB = b2[1];
    {
        ulonglong2 w01 = w2[0], w23 = w2[1];          // k = 0, bias addend
#pragma unroll
        for (int r = 0; r < 4; r++) {
            u64 xd = pkdup(cf[r][0]);
            a[r][0] = ffma2(w01.x, xd, bA.x);
            a[r][1] = ffma2(w01.y, xd, bA.y);
            a[r][2] = ffma2(w23.x, xd, bB.x);
            a[r][3] = ffma2(w23.y, xd, bB.y);
        }
    }
#pragma unroll
    for (int k = 1; k < 8; k++) {
        ulonglong2 w01 = w2[k * 2], w23 = w2[k * 2 + 1];
#pragma unroll
        for (int r = 0; r < 4; r++) {
            u64 xd = pkdup(cf[r][k]);
            a[r][0] = ffma2(w01.x, xd, a[r][0]);      // 16 independent chains
            a[r][1] = ffma2(w01.y, xd, a[r][1]);
            a[r][2] = ffma2(w23.x, xd, a[r][2]);
            a[r][3] = ffma2(w23.y, xd, a[r][3]);
        }
    }
}

// Fused layer-0 for BOTH MLPs (shared input -> shared dup-MOVs).
__device__ __forceinline__ void layer0_fused(const u64* __restrict__ sW, const u64* __restrict__ sB,
                                             const float zf[4][8], u64 aL[4][4], u64 aB[4][4]) {
    const ulonglong2* wL = reinterpret_cast<const ulonglong2*>(sW);            // mat 0
    const ulonglong2* wB = reinterpret_cast<const ulonglong2*>(sW + 5 * 32);   // mat 5
    const ulonglong2* bL = reinterpret_cast<const ulonglong2*>(sB);
    const ulonglong2* bB = reinterpret_cast<const ulonglong2*>(sB + 5 * 4);
    ulonglong2 bL01 = bL[0], bL23 = bL[1], bB01 = bB[0], bB23 = bB[1];
    {
        ulonglong2 l01 = wL[0], l23 = wL[1], m01 = wB[0], m23 = wB[1];
#pragma unroll
        for (int r = 0; r < 4; r++) {
            u64 xd = pkdup(zf[r][0]);
            aL[r][0] = ffma2(l01.x, xd, bL01.x); aL[r][1] = ffma2(l01.y, xd, bL01.y);
            aL[r][2] = ffma2(l23.x, xd, bL23.x); aL[r][3] = ffma2(l23.y, xd, bL23.y);
            aB[r][0] = ffma2(m01.x, xd, bB01.x); aB[r][1] = ffma2(m01.y, xd, bB01.y);
            aB[r][2] = ffma2(m23.x, xd, bB23.x); aB[r][3] = ffma2(m23.y, xd, bB23.y);
        }
    }
#pragma unroll
    for (int k = 1; k < 8; k++) {
        ulonglong2 l01 = wL[k * 2], l23 = wL[k * 2 + 1];
        ulonglong2 m01 = wB[k * 2], m23 = wB[k * 2 + 1];
#pragma unroll
        for (int r = 0; r < 4; r++) {
            u64 xd = pkdup(zf[r][k]);
            aL[r][0] = ffma2(l01.x, xd, aL[r][0]); aL[r][1] = ffma2(l01.y, xd, aL[r][1]);
            aL[r][2] = ffma2(l23.x, xd, aL[r][2]); aL[r][3] = ffma2(l23.y, xd, aL[r][3]);
            aB[r][0] = ffma2(m01.x, xd, aB[r][0]); aB[r][1] = ffma2(m01.y, xd, aB[r][1]);
            aB[r][2] = ffma2(m23.x, xd, aB[r][2]); aB[r][3] = ffma2(m23.y, xd, aB[r][3]);
        }
    }
}

// unpack accumulators + exact scalar leaky-relu (FMUL + FMNMX)
__device__ __forceinline__ void act4(const u64 a[4][4], float cf[4][8]) {
#pragma unroll
    for (int r = 0; r < 4; r++)
#pragma unroll
        for (int j2 = 0; j2 < 4; j2++) {
            float lo, hi; upk2(a[r][j2], lo, hi);
            cf[r][2 * j2]     = fmaxf(lo, LRSLOPE * lo);
            cf[r][2 * j2 + 1] = fmaxf(hi, LRSLOPE * hi);
        }
}

// scalar reference path for tail rows (<=3 threads, never hot)
__device__ void scalar_mlp(const u64* sW, const u64* sB, int mbase,
                           const float in[8], float out[8]) {
    float c[8];
    for (int j = 0; j < 8; j++) c[j] = in[j];
    for (int l = 0; l < 5; l++) {
        float a[8];
        for (int j2 = 0; j2 < 4; j2++) {
            float lo, hi; upk2(sB[(mbase + l) * 4 + j2], lo, hi);
            a[2 * j2] = lo; a[2 * j2 + 1] = hi;
        }
        for (int k = 0; k < 8; k++)
            for (int j2 = 0; j2 < 4; j2++) {
                float lo, hi; upk2(sW[((mbase + l) * 8 + k) * 4 + j2], lo, hi);
                a[2 * j2]     += lo * c[k];
                a[2 * j2 + 1] += hi * c[k];
            }
        if (l < 4)
            for (int j = 0; j < 8; j++) c[j] = fmaxf(a[j], LRSLOPE * a[j]);
        else
            for (int j = 0; j < 8; j++) out[j] = a[j];
    }
}

__global__ void __launch_bounds__(256, 2)
affine_coupling_kernel(const ulonglong2* __restrict__ z2, ulonglong2* __restrict__ o2,
                       int batch, Params P) {
    __shared__ __align__(16) u64 sW[320];   // 10 mats * 8k * 4 (j-packed pairs)
    __shared__ __align__(16) u64 sB[40];    // 10 mats * 4

    for (int i = threadIdx.x; i < 320; i += blockDim.x) {
        int mat = i >> 5, r = i & 31, k = r >> 2, j2 = r & 3;
        sW[i] = pk2(P.W[mat][(2 * j2) * 8 + k], P.W[mat][(2 * j2 + 1) * 8 + k]);
    }
    for (int i = threadIdx.x; i < 40; i += blockDim.x) {
        int mat = i >> 2, j2 = i & 3;
        sB[i] = pk2(P.B[mat][2 * j2], P.B[mat][2 * j2 + 1]);
    }
    __syncthreads();

    const int t = blockIdx.x * blockDim.x + threadIdx.x;
    const int q = batch >> 2;

    if (t < q) {
        int rows[4] = { t, t + q, t + 2 * q, t + 3 * q };

        // ---- Phase 1: load zl halves (rows are 4 ulonglong2; left = [0],[1]) ----
        float zf[4][8];
#pragma unroll
        for (int r = 0; r < 4; r++) {
            ulonglong2 L0 = z2[(size_t)rows[r] * 4 + 0];
            ulonglong2 L1 = z2[(size_t)rows[r] * 4 + 1];
            // left-half output = copy of zl: store NOW, free the regs
            o2[(size_t)rows[r] * 4 + 0] = L0;
            o2[(size_t)rows[r] * 4 + 1] = L1;
            upk2(L0.x, zf[r][0], zf[r][1]);
            upk2(L0.y, zf[r][2], zf[r][3]);
            upk2(L1.x, zf[r][4], zf[r][5]);
            upk2(L1.y, zf[r][6], zf[r][7]);
        }

        // ---- Phase 2: both MLPs, layer-0 fused ----
        u64 aL[4][4], aB[4][4];
        layer0_fused(sW, sB, zf, aL, aB);            // zl dead after this

        float cL[4][8], cB[4][8];
        act4(aL, cL);
        act4(aB, cB);

#pragma unroll
        for (int l = 1; l < 4; l++) { layer4(sW + l * 32, sB + l * 4, cL, aL); act4(aL, cL); }
        layer4(sW + 4 * 32, sB + 4 * 4, cL, aL);     // aL = log_s (no activation)

#pragma unroll
        for (int l = 1; l < 4; l++) { layer4(sW + (5 + l) * 32, sB + (5 + l) * 4, cB, aB); act4(aB, cB); }
        layer4(sW + 9 * 32, sB + 9 * 4, cB, aB);     // aB = b

        // ---- Phase 3: late-load zr, fuse y = exp(ls)*zr + b, store right half ----
#pragma unroll
        for (int r = 0; r < 4; r++) {
            ulonglong2 R0 = z2[(size_t)rows[r] * 4 + 2];   // zr pairs, j-consecutive
            ulonglong2 R1 = z2[(size_t)rows[r] * 4 + 3];
            float a, b;
            ulonglong2 Y0, Y1;
            upk2(aL[r][0], a, b); Y0.x = ffma2(pk2(__expf(a), __expf(b)), R0.x, aB[r][0]);
            upk2(aL[r][1], a, b); Y0.y = ffma2(pk2(__expf(a), __expf(b)), R0.y, aB[r][1]);
            upk2(aL[r][2], a, b); Y1.x = ffma2(pk2(__expf(a), __expf(b)), R1.x, aB[r][2]);
            upk2(aL[r][3], a, b); Y1.y = ffma2(pk2(__expf(a), __expf(b)), R1.y, aB[r][3]);
            o2[(size_t)rows[r] * 4 + 2] = Y0;
            o2[(size_t)rows[r] * 4 + 3] = Y1;
        }
    }

    // Tail rows (batch % 4 != 0): at most 3 rows; correctness-only path.
    const int tail_start = q << 2;
    if (t < batch - tail_start) {
        const int r = tail_start + t;
        const float* zrow = reinterpret_cast<const float*>(z2) + (size_t)r * 16;
        float in[8], ls[8], bb[8];
        for (int j = 0; j < 8; j++) in[j] = zrow[j];
        scalar_mlp(sW, sB, 0, in, ls);
        scalar_mlp(sW, sB, 5, in, bb);
        float* orow = reinterpret_cast<float*>(o2) + (size_t)r * 16;
        for (int j = 0; j < 8; j++) {
            orow[j] = zrow[j];
            orow[8 + j] = __expf(ls[j]) * zrow[8 + j] + bb[j];
        }
    }
}

extern "C" void kernel_launch(void* const* d_in, const int* in_sizes, int n_in,
                              void* d_out, int out_size) {
    // ---- Robust input parsing (by size signature; handles stacked (320/40)
    // and per-matrix (64/8) flattenings; z = largest input). ----
    int zi = 0;
    for (int i = 1; i < n_in; i++)
        if (in_sizes[i] > in_sizes[zi]) zi = i;
    const float* z = (const float*)d_in[zi];
    int batch = in_sizes[zi] / 16;

    Params P;
    const float* wlist[10]; int wn = 0;   // order encountered: ws_logs then ws_b
    const float* blist[10]; int bn = 0;   // order encountered: bs_logs then bs_b
    for (int i = 0; i < n_in; i++) {
        if (i == zi) continue;
        const float* p = (const float*)d_in[i];
        int sz = in_sizes[i];
        if (sz == 320) { for (int m = 0; m < 5 && wn < 10; m++) wlist[wn++] = p + m * 64; }
        else if (sz == 64) { if (wn < 10) wlist[wn++] = p; }
        else if (sz == 40) { for (int m = 0; m < 5 && bn < 10; m++) blist[bn++] = p + m * 8; }
        else if (sz == 8)  { if (bn < 10) blist[bn++] = p; }
    }
    for (int i = 0; i < 10; i++) { P.W[i] = wlist[i]; P.B[i] = blist[i]; }

    int q = batch >> 2;
    int tail = batch - (q << 2);
    int work = q > tail ? q : tail;
    if (work < 1) work = 1;
    int threads = 256;
    int blocks = (work + threads - 1) / threads;
    affine_coupling_kernel<<<blocks, threads>>>((const ulonglong2*)z, (ulonglong2*)d_out, batch, P);
}

// round 16
// speedup vs baseline: 1.8626x; 1.1392x over previous
#include <cuda_runtime.h>

typedef unsigned long long u64;

#define LRSLOPE 0.01f

__device__ __forceinline__ u64 pk2(float lo, float hi) {
    u64 r; asm("mov.b64 %0, {%1, %2};" : "=l"(r) : "f"(lo), "f"(hi)); return r;
}
__device__ __forceinline__ void upk2(u64 v, float& lo, float& hi) {
    asm("mov.b64 {%0, %1}, %2;" : "=f"(lo), "=f"(hi) : "l"(v));
}
// duplicate one float into both halves of a packed f32x2 register
__device__ __forceinline__ u64 pkdup(float x) {
    u64 r; asm("mov.b64 %0, {%1, %1};" : "=l"(r) : "f"(x)); return r;
}
// Packed f32x2 FMA (sm_100+): r = a*b + c on both 32-bit halves.
__device__ __forceinline__ u64 ffma2(u64 a, u64 b, u64 c) {
    u64 r; asm("fma.rn.f32x2 %0, %1, %2, %3;" : "=l"(r) : "l"(a), "l"(b), "l"(c)); return r;
}

struct Params {
    const float* W[10];   // 0..4 = ws_logs, 5..9 = ws_b   (each 8x8, row-major [out][in])
    const float* B[10];   // 0..4 = bs_logs, 5..9 = bs_b   (each 8)
};

// ---- Constant-memory weight bank (block-uniform -> constant port, NOT L1) ----
// Layout (j-packed, non-duplicated):
//   cAll[(mat*8 + k)*2 + h] : .x = pk2(W[mat][4h  ][k], W[mat][4h+1][k])
//                             .y = pk2(W[mat][4h+2][k], W[mat][4h+3][k])
//   cAll[160 + mat*2 + h]   : .x = pk2(B[mat][4h], B[mat][4h+1])
//                             .y = pk2(B[mat][4h+2], B[mat][4h+3])
__constant__ ulonglong2 cAll[180];
__device__   ulonglong2 g_pack[180];   // staging, filled by pack_kernel

__global__ void pack_kernel(Params P) {
    int i = threadIdx.x;
    if (i >= 180) return;
    ulonglong2 o;
    if (i < 160) {
        int m = i >> 4, r = i & 15, k = r >> 1, h = r & 1;
        o.x = pk2(P.W[m][(4 * h + 0) * 8 + k], P.W[m][(4 * h + 1) * 8 + k]);
        o.y = pk2(P.W[m][(4 * h + 2) * 8 + k], P.W[m][(4 * h + 3) * 8 + k]);
    } else {
        int q = i - 160, m = q >> 1, h = q & 1;
        o.x = pk2(P.B[m][4 * h + 0], P.B[m][4 * h + 1]);
        o.y = pk2(P.B[m][4 * h + 2], P.B[m][4 * h + 3]);
    }
    g_pack[i] = o;
}

// One layer on 4 independent rows; acc a[r][j2] packs outputs (2*j2, 2*j2+1).
// Bias is the k=0 FFMA2 addend. Weights come from the constant port.
__device__ __forceinline__ void layer4(int mat, const float cf[4][8], u64 a[4][4]) {
    const int wb = mat * 16;            // (mat*8+k)*2 with k=0
    ulonglong2 bA = cAll[160 + mat * 2 + 0];
    ulonglong2 bB = cAll[160 + mat * 2 + 1];
    {
        ulonglong2 w01 = cAll[wb + 0], w23 = cAll[wb + 1];   // k = 0
#pragma unroll
        for (int r = 0; r < 4; r++) {
            u64 xd = pkdup(cf[r][0]);
            a[r][0] = ffma2(w01.x, xd, bA.x);
            a[r][1] = ffma2(w01.y, xd, bA.y);
            a[r][2] = ffma2(w23.x, xd, bB.x);
            a[r][3] = ffma2(w23.y, xd, bB.y);
        }
    }
#pragma unroll
    for (int k = 1; k < 8; k++) {
        ulonglong2 w01 = cAll[wb + k * 2], w23 = cAll[wb + k * 2 + 1];
#pragma unroll
        for (int r = 0; r < 4; r++) {
            u64 xd = pkdup(cf[r][k]);
            a[r][0] = ffma2(w01.x, xd, a[r][0]);      // 16 independent chains
            a[r][1] = ffma2(w01.y, xd, a[r][1]);
            a[r][2] = ffma2(w23.x, xd, a[r][2]);
            a[r][3] = ffma2(w23.y, xd, a[r][3]);
        }
    }
}

// Fused layer-0 for BOTH MLPs (mats 0 and 5; shared input -> shared dup-MOVs).
__device__ __forceinline__ void layer0_fused(const float zf[4][8], u64 aL[4][4], u64 aB[4][4]) {
    ulonglong2 bL01 = cAll[160 + 0], bL23 = cAll[160 + 1];
    ulonglong2 bB01 = cAll[160 + 10], bB23 = cAll[160 + 11];
    {
        ulonglong2 l01 = cAll[0], l23 = cAll[1];
        ulonglong2 m01 = cAll[80], m23 = cAll[81];           // mat 5 base = 5*16
#pragma unroll
        for (int r = 0; r < 4; r++) {
            u64 xd = pkdup(zf[r][0]);
            aL[r][0] = ffma2(l01.x, xd, bL01.x); aL[r][1] = ffma2(l01.y, xd, bL01.y);
            aL[r][2] = ffma2(l23.x, xd, bL23.x); aL[r][3] = ffma2(l23.y, xd, bL23.y);
            aB[r][0] = ffma2(m01.x, xd, bB01.x); aB[r][1] = ffma2(m01.y, xd, bB01.y);
            aB[r][2] = ffma2(m23.x, xd, bB23.x); aB[r][3] = ffma2(m23.y, xd, bB23.y);
        }
    }
#pragma unroll
    for (int k = 1; k < 8; k++) {
        ulonglong2 l01 = cAll[k * 2], l23 = cAll[k * 2 + 1];
        ulonglong2 m01 = cAll[80 + k * 2], m23 = cAll[80 + k * 2 + 1];
#pragma unroll
        for (int r = 0; r < 4; r++) {
            u64 xd = pkdup(zf[r][k]);
            aL[r][0] = ffma2(l01.x, xd, aL[r][0]); aL[r][1] = ffma2(l01.y, xd, aL[r][1]);
            aL[r][2] = ffma2(l23.x, xd, aL[r][2]); aL[r][3] = ffma2(l23.y, xd, aL[r][3]);
            aB[r][0] = ffma2(m01.x, xd, aB[r][0]); aB[r][1] = ffma2(m01.y, xd, aB[r][1]);
            aB[r][2] = ffma2(m23.x, xd, aB[r][2]); aB[r][3] = ffma2(m23.y, xd, aB[r][3]);
        }
    }
}

// unpack accumulators + exact scalar leaky-relu (FMUL + FMNMX)
__device__ __forceinline__ void act4(const u64 a[4][4], float cf[4][8]) {
#pragma unroll
    for (int r = 0; r < 4; r++)
#pragma unroll
        for (int j2 = 0; j2 < 4; j2++) {
            float lo, hi; upk2(a[r][j2], lo, hi);
            cf[r][2 * j2]     = fmaxf(lo, LRSLOPE * lo);
            cf[r][2 * j2 + 1] = fmaxf(hi, LRSLOPE * hi);
        }
}

// scalar reference path for tail rows (<=3 threads, never hot)
__device__ void scalar_mlp(int mbase, const float in[8], float out[8]) {
    float c[8];
    for (int j = 0; j < 8; j++) c[j] = in[j];
    for (int l = 0; l < 5; l++) {
        int mat = mbase + l;
        float a[8];
        for (int h = 0; h < 2; h++) {
            ulonglong2 bv = cAll[160 + mat * 2 + h];
            float lo, hi;
            upk2(bv.x, lo, hi); a[4 * h + 0] = lo; a[4 * h + 1] = hi;
            upk2(bv.y, lo, hi); a[4 * h + 2] = lo; a[4 * h + 3] = hi;
        }
        for (int k = 0; k < 8; k++)
            for (int h = 0; h < 2; h++) {
                ulonglong2 wv = cAll[(mat * 8 + k) * 2 + h];
                float lo, hi;
                upk2(wv.x, lo, hi); a[4 * h + 0] += lo * c[k]; a[4 * h + 1] += hi * c[k];
                upk2(wv.y, lo, hi); a[4 * h + 2] += lo * c[k]; a[4 * h + 3] += hi * c[k];
            }
        if (l < 4)
            for (int j = 0; j < 8; j++) c[j] = fmaxf(a[j], LRSLOPE * a[j]);
        else
            for (int j = 0; j < 8; j++) out[j] = a[j];
    }
}

__global__ void __launch_bounds__(256, 2)
affine_coupling_kernel(const ulonglong2* __restrict__ z2, ulonglong2* __restrict__ o2,
                       int batch) {
    const int t = blockIdx.x * blockDim.x + threadIdx.x;
    const int q = batch >> 2;

    if (t < q) {
        int rows[4] = { t, t + q, t + 2 * q, t + 3 * q };

        // ---- Phase 1: load zl halves (rows are 4 ulonglong2; left = [0],[1]) ----
        float zf[4][8];
#pragma unroll
        for (int r = 0; r < 4; r++) {
            ulonglong2 L0 = z2[(size_t)rows[r] * 4 + 0];
            ulonglong2 L1 = z2[(size_t)rows[r] * 4 + 1];
            // left-half output = copy of zl: store NOW, free the regs
            o2[(size_t)rows[r] * 4 + 0] = L0;
            o2[(size_t)rows[r] * 4 + 1] = L1;
            upk2(L0.x, zf[r][0], zf[r][1]);
            upk2(L0.y, zf[r][2], zf[r][3]);
            upk2(L1.x, zf[r][4], zf[r][5]);
            upk2(L1.y, zf[r][6], zf[r][7]);
        }

        // ---- Phase 2: both MLPs, layer-0 fused; weights via constant port ----
        u64 aL[4][4], aB[4][4];
        layer0_fused(zf, aL, aB);                    // zl dead after this

        float cL[4][8], cB[4][8];
        act4(aL, cL);
        act4(aB, cB);

#pragma unroll
        for (int l = 1; l < 4; l++) { layer4(l, cL, aL); act4(aL, cL); }
        layer4(4, cL, aL);                           // aL = log_s (no activation)

#pragma unroll
        for (int l = 1; l < 4; l++) { layer4(5 + l, cB, aB); act4(aB, cB); }
        layer4(9, cB, aB);                           // aB = b

        // ---- Phase 3: late-load zr, fuse y = exp(ls)*zr + b, store right half ----
#pragma unroll
        for (int r = 0; r < 4; r++) {
            ulonglong2 R0 = z2[(size_t)rows[r] * 4 + 2];   // zr pairs, j-consecutive
            ulonglong2 R1 = z2[(size_t)rows[r] * 4 + 3];
            float a, b;
            ulonglong2 Y0, Y1;
            upk2(aL[r][0], a, b); Y0.x = ffma2(pk2(__expf(a), __expf(b)), R0.x, aB[r][0]);
            upk2(aL[r][1], a, b); Y0.y = ffma2(pk2(__expf(a), __expf(b)), R0.y, aB[r][1]);
            upk2(aL[r][2], a, b); Y1.x = ffma2(pk2(__expf(a), __expf(b)), R1.x, aB[r][2]);
            upk2(aL[r][3], a, b); Y1.y = ffma2(pk2(__expf(a), __expf(b)), R1.y, aB[r][3]);
            o2[(size_t)rows[r] * 4 + 2] = Y0;
            o2[(size_t)rows[r] * 4 + 3] = Y1;
        }
    }

    // Tail rows (batch % 4 != 0): at most 3 rows; correctness-only path.
    const int tail_start = q << 2;
    if (t < batch - tail_start) {
        const int r = tail_start + t;
        const float* zrow = reinterpret_cast<const float*>(z2) + (size_t)r * 16;
        float in[8], ls[8], bb[8];
        for (int j = 0; j < 8; j++) in[j] = zrow[j];
        scalar_mlp(0, in, ls);
        scalar_mlp(5, in, bb);
        float* orow = reinterpret_cast<float*>(o2) + (size_t)r * 16;
        for (int j = 0; j < 8; j++) {
            orow[j] = zrow[j];
            orow[8 + j] = __expf(ls[j]) * zrow[8 + j] + bb[j];
        }
    }
}

extern "C" void kernel_launch(void* const* d_in, const int* in_sizes, int n_in,
                              void* d_out, int out_size) {
    // ---- Robust input parsing (by size signature; handles stacked (320/40)
    // and per-matrix (64/8) flattenings; z = largest input). ----
    int zi = 0;
    for (int i = 1; i < n_in; i++)
        if (in_sizes[i] > in_sizes[zi]) zi = i;
    const float* z = (const float*)d_in[zi];
    int batch = in_sizes[zi] / 16;

    Params P;
    const float* wlist[10]; int wn = 0;   // order encountered: ws_logs then ws_b
    const float* blist[10]; int bn = 0;   // order encountered: bs_logs then bs_b
    for (int i = 0; i < n_in; i++) {
        if (i == zi) continue;
        const float* p = (const float*)d_in[i];
        int sz = in_sizes[i];
        if (sz == 320) { for (int m = 0; m < 5 && wn < 10; m++) wlist[wn++] = p + m * 64; }
        else if (sz == 64) { if (wn < 10) wlist[wn++] = p; }
        else if (sz == 40) { for (int m = 0; m < 5 && bn < 10; m++) blist[bn++] = p + m * 8; }
        else if (sz == 8)  { if (bn < 10) blist[bn++] = p; }
    }
    for (int i = 0; i < 10; i++) { P.W[i] = wlist[i]; P.B[i] = blist[i]; }

    // 1) pack weights into device staging, 2) D2D copy staging -> __constant__
    //    using REAL device addresses (cudaGetSymbolAddress — the R14 bug was
    //    passing the __device__ shadow symbol as a pointer), 3) main kernel.
    // All graph-capturable: kernel node, memcpy node (D2D), kernel node.
    pack_kernel<<<1, 192>>>(P);
    void* dst = nullptr;
    void* src = nullptr;
    cudaGetSymbolAddress(&dst, cAll);
    cudaGetSymbolAddress(&src, g_pack);
    cudaMemcpyAsync(dst, src, sizeof(ulonglong2) * 180, cudaMemcpyDeviceToDevice, 0);

    int q = batch >> 2;
    int tail = batch - (q << 2);
    int work = q > tail ? q : tail;
    if (work < 1) work = 1;
    int threads = 256;
    int blocks = (work + threads - 1) / threads;
    affine_coupling_kernel<<<blocks, threads>>>((const ulonglong2*)z, (ulonglong2*)d_out, batch);
}

// round 17
// speedup vs baseline: 1.9678x; 1.0565x over previous
#include <cuda_runtime.h>

typedef unsigned long long u64;

#define LRSLOPE 0.01f

__device__ __forceinline__ u64 pk2(float lo, float hi) {
    u64 r; asm("mov.b64 %0, {%1, %2};" : "=l"(r) : "f"(lo), "f"(hi)); return r;
}
__device__ __forceinline__ void upk2(u64 v, float& lo, float& hi) {
    asm("mov.b64 {%0, %1}, %2;" : "=f"(lo), "=f"(hi) : "l"(v));
}
// duplicate one float into both halves of a packed f32x2 register
__device__ __forceinline__ u64 pkdup(float x) {
    u64 r; asm("mov.b64 %0, {%1, %1};" : "=l"(r) : "f"(x)); return r;
}
// Packed f32x2 FMA (sm_100+): r = a*b + c on both 32-bit halves.
__device__ __forceinline__ u64 ffma2(u64 a, u64 b, u64 c) {
    u64 r; asm("fma.rn.f32x2 %0, %1, %2, %3;" : "=l"(r) : "l"(a), "l"(b), "l"(c)); return r;
}

struct Params {
    const float* W[10];   // 0..4 = ws_logs, 5..9 = ws_b   (each 8x8, row-major [out][in])
    const float* B[10];   // 0..4 = bs_logs, 5..9 = bs_b   (each 8)
};

// ---- Constant-memory weight bank (block-uniform -> constant port, NOT L1) ----
// Layout (j-packed, non-duplicated):
//   cAll[(mat*8 + k)*2 + h] : .x = pk2(W[mat][4h  ][k], W[mat][4h+1][k])
//                             .y = pk2(W[mat][4h+2][k], W[mat][4h+3][k])
//   cAll[160 + mat*2 + h]   : .x = pk2(B[mat][4h], B[mat][4h+1])
//                             .y = pk2(B[mat][4h+2], B[mat][4h+3])
__constant__ ulonglong2 cAll[180];
__device__   ulonglong2 g_pack[180];   // staging, filled by pack_kernel

__global__ void pack_kernel(Params P) {
    int i = threadIdx.x;
    if (i >= 180) return;
    ulonglong2 o;
    if (i < 160) {
        int m = i >> 4, r = i & 15, k = r >> 1, h = r & 1;
        o.x = pk2(P.W[m][(4 * h + 0) * 8 + k], P.W[m][(4 * h + 1) * 8 + k]);
        o.y = pk2(P.W[m][(4 * h + 2) * 8 + k], P.W[m][(4 * h + 3) * 8 + k]);
    } else {
        int q = i - 160, m = q >> 1, h = q & 1;
        o.x = pk2(P.B[m][4 * h + 0], P.B[m][4 * h + 1]);
        o.y = pk2(P.B[m][4 * h + 2], P.B[m][4 * h + 3]);
    }
    g_pack[i] = o;
}

// One layer on 4 independent rows; acc a[r][j2] packs outputs (2*j2, 2*j2+1).
// Bias is the k=0 FFMA2 addend. Weights come from the constant port.
__device__ __forceinline__ void layer4(int mat, const float cf[4][8], u64 a[4][4]) {
    const int wb = mat * 16;            // (mat*8+k)*2 with k=0
    ulonglong2 bA = cAll[160 + mat * 2 + 0];
    ulonglong2 bB = cAll[160 + mat * 2 + 1];
    {
        ulonglong2 w01 = cAll[wb + 0], w23 = cAll[wb + 1];   // k = 0
#pragma unroll
        for (int r = 0; r < 4; r++) {
            u64 xd = pkdup(cf[r][0]);
            a[r][0] = ffma2(w01.x, xd, bA.x);
            a[r][1] = ffma2(w01.y, xd, bA.y);
            a[r][2] = ffma2(w23.x, xd, bB.x);
            a[r][3] = ffma2(w23.y, xd, bB.y);
        }
    }
#pragma unroll
    for (int k = 1; k < 8; k++) {
        ulonglong2 w01 = cAll[wb + k * 2], w23 = cAll[wb + k * 2 + 1];
#pragma unroll
        for (int r = 0; r < 4; r++) {
            u64 xd = pkdup(cf[r][k]);
            a[r][0] = ffma2(w01.x, xd, a[r][0]);      // 16 independent chains
            a[r][1] = ffma2(w01.y, xd, a[r][1]);
            a[r][2] = ffma2(w23.x, xd, a[r][2]);
            a[r][3] = ffma2(w23.y, xd, a[r][3]);
        }
    }
}

// Fused layer-0 for BOTH MLPs (mats 0 and 5; shared input -> shared dup-MOVs).
__device__ __forceinline__ void layer0_fused(const float zf[4][8], u64 aL[4][4], u64 aB[4][4]) {
    ulonglong2 bL01 = cAll[160 + 0], bL23 = cAll[160 + 1];
    ulonglong2 bB01 = cAll[160 + 10], bB23 = cAll[160 + 11];
    {
        ulonglong2 l01 = cAll[0], l23 = cAll[1];
        ulonglong2 m01 = cAll[80], m23 = cAll[81];           // mat 5 base = 5*16
#pragma unroll
        for (int r = 0; r < 4; r++) {
            u64 xd = pkdup(zf[r][0]);
            aL[r][0] = ffma2(l01.x, xd, bL01.x); aL[r][1] = ffma2(l01.y, xd, bL01.y);
            aL[r][2] = ffma2(l23.x, xd, bL23.x); aL[r][3] = ffma2(l23.y, xd, bL23.y);
            aB[r][0] = ffma2(m01.x, xd, bB01.x); aB[r][1] = ffma2(m01.y, xd, bB01.y);
            aB[r][2] = ffma2(m23.x, xd, bB23.x); aB[r][3] = ffma2(m23.y, xd, bB23.y);
        }
    }
#pragma unroll
    for (int k = 1; k < 8; k++) {
        ulonglong2 l01 = cAll[k * 2], l23 = cAll[k * 2 + 1];
        ulonglong2 m01 = cAll[80 + k * 2], m23 = cAll[80 + k * 2 + 1];
#pragma unroll
        for (int r = 0; r < 4; r++) {
            u64 xd = pkdup(zf[r][k]);
            aL[r][0] = ffma2(l01.x, xd, aL[r][0]); aL[r][1] = ffma2(l01.y, xd, aL[r][1]);
            aL[r][2] = ffma2(l23.x, xd, aL[r][2]); aL[r][3] = ffma2(l23.y, xd, aL[r][3]);
            aB[r][0] = ffma2(m01.x, xd, aB[r][0]); aB[r][1] = ffma2(m01.y, xd, aB[r][1]);
            aB[r][2] = ffma2(m23.x, xd, aB[r][2]); aB[r][3] = ffma2(m23.y, xd, aB[r][3]);
        }
    }
}

// unpack accumulators + exact scalar leaky-relu (FMUL + FMNMX)
__device__ __forceinline__ void act4(const u64 a[4][4], float cf[4][8]) {
#pragma unroll
    for (int r = 0; r < 4; r++)
#pragma unroll
        for (int j2 = 0; j2 < 4; j2++) {
            float lo, hi; upk2(a[r][j2], lo, hi);
            cf[r][2 * j2]     = fmaxf(lo, LRSLOPE * lo);
            cf[r][2 * j2 + 1] = fmaxf(hi, LRSLOPE * hi);
        }
}

// scalar reference path for tail rows (<=3 threads, never hot)
__device__ void scalar_mlp(int mbase, const float in[8], float out[8]) {
    float c[8];
    for (int j = 0; j < 8; j++) c[j] = in[j];
    for (int l = 0; l < 5; l++) {
        int mat = mbase + l;
        float a[8];
        for (int h = 0; h < 2; h++) {
            ulonglong2 bv = cAll[160 + mat * 2 + h];
            float lo, hi;
            upk2(bv.x, lo, hi); a[4 * h + 0] = lo; a[4 * h + 1] = hi;
            upk2(bv.y, lo, hi); a[4 * h + 2] = lo; a[4 * h + 3] = hi;
        }
        for (int k = 0; k < 8; k++)
            for (int h = 0; h < 2; h++) {
                ulonglong2 wv = cAll[(mat * 8 + k) * 2 + h];
                float lo, hi;
                upk2(wv.x, lo, hi); a[4 * h + 0] += lo * c[k]; a[4 * h + 1] += hi * c[k];
                upk2(wv.y, lo, hi); a[4 * h + 2] += lo * c[k]; a[4 * h + 3] += hi * c[k];
            }
        if (l < 4)
            for (int j = 0; j < 8; j++) c[j] = fmaxf(a[j], LRSLOPE * a[j]);
        else
            for (int j = 0; j < 8; j++) out[j] = a[j];
    }
}

__global__ void __launch_bounds__(256, 2)
affine_coupling_kernel(const ulonglong2* __restrict__ z2, ulonglong2* __restrict__ o2,
                       int batch) {
    const int t = blockIdx.x * blockDim.x + threadIdx.x;
    const int q = batch >> 2;

    if (t < q) {
        int rows[4] = { t, t + q, t + 2 * q, t + 3 * q };

        // ---- Phase 1: load zl halves (rows are 4 ulonglong2; left = [0],[1]) ----
        float zf[4][8];
#pragma unroll
        for (int r = 0; r < 4; r++) {
            ulonglong2 L0 = z2[(size_t)rows[r] * 4 + 0];
            ulonglong2 L1 = z2[(size_t)rows[r] * 4 + 1];
            // left-half output = copy of zl: store NOW, free the regs
            o2[(size_t)rows[r] * 4 + 0] = L0;
            o2[(size_t)rows[r] * 4 + 1] = L1;
            upk2(L0.x, zf[r][0], zf[r][1]);
            upk2(L0.y, zf[r][2], zf[r][3]);
            upk2(L1.x, zf[r][4], zf[r][5]);
            upk2(L1.y, zf[r][6], zf[r][7]);
        }

        // ---- Phase 2: both MLPs, layer-0 fused; weights via constant port ----
        u64 aL[4][4], aB[4][4];
        layer0_fused(zf, aL, aB);                    // zl dead after this

        float cL[4][8], cB[4][8];
        act4(aL, cL);
        act4(aB, cB);

#pragma unroll
        for (int l = 1; l < 4; l++) { layer4(l, cL, aL); act4(aL, cL); }
        layer4(4, cL, aL);                           // aL = log_s (no activation)

#pragma unroll
        for (int l = 1; l < 4; l++) { layer4(5 + l, cB, aB); act4(aB, cB); }
        layer4(9, cB, aB);                           // aB = b

        // ---- Phase 3: late-load zr, fuse y = exp(ls)*zr + b, store right half ----
#pragma unroll
        for (int r = 0; r < 4; r++) {
            ulonglong2 R0 = z2[(size_t)rows[r] * 4 + 2];   // zr pairs, j-consecutive
            ulonglong2 R1 = z2[(size_t)rows[r] * 4 + 3];
            float a, b;
            ulonglong2 Y0, Y1;
            upk2(aL[r][0], a, b); Y0.x = ffma2(pk2(__expf(a), __expf(b)), R0.x, aB[r][0]);
            upk2(aL[r][1], a, b); Y0.y = ffma2(pk2(__expf(a), __expf(b)), R0.y, aB[r][1]);
            upk2(aL[r][2], a, b); Y1.x = ffma2(pk2(__expf(a), __expf(b)), R1.x, aB[r][2]);
            upk2(aL[r][3], a, b); Y1.y = ffma2(pk2(__expf(a), __expf(b)), R1.y, aB[r][3]);
            o2[(size_t)rows[r] * 4 + 2] = Y0;
            o2[(size_t)rows[r] * 4 + 3] = Y1;
        }
    }

    // Tail rows (batch % 4 != 0): at most 3 rows; correctness-only path.
    const int tail_start = q << 2;
    if (t < batch - tail_start) {
        const int r = tail_start + t;
        const float* zrow = reinterpret_cast<const float*>(z2) + (size_t)r * 16;
        float in[8], ls[8], bb[8];
        for (int j = 0; j < 8; j++) in[j] = zrow[j];
        scalar_mlp(0, in, ls);
        scalar_mlp(5, in, bb);
        float* orow = reinterpret_cast<float*>(o2) + (size_t)r * 16;
        for (int j = 0; j < 8; j++) {
            orow[j] = zrow[j];
            orow[8 + j] = __expf(ls[j]) * zrow[8 + j] + bb[j];
        }
    }
}

extern "C" void kernel_launch(void* const* d_in, const int* in_sizes, int n_in,
                              void* d_out, int out_size) {
    // ---- Robust input parsing (by size signature; handles stacked (320/40)
    // and per-matrix (64/8) flattenings; z = largest input). ----
    int zi = 0;
    for (int i = 1; i < n_in; i++)
        if (in_sizes[i] > in_sizes[zi]) zi = i;
    const float* z = (const float*)d_in[zi];
    int batch = in_sizes[zi] / 16;

    Params P;
    const float* wlist[10]; int wn = 0;   // order encountered: ws_logs then ws_b
    const float* blist[10]; int bn = 0;   // order encountered: bs_logs then bs_b
    for (int i = 0; i < n_in; i++) {
        if (i == zi) continue;
        const float* p = (const float*)d_in[i];
        int sz = in_sizes[i];
        if (sz == 320) { for (int m = 0; m < 5 && wn < 10; m++) wlist[wn++] = p + m * 64; }
        else if (sz == 64) { if (wn < 10) wlist[wn++] = p; }
        else if (sz == 40) { for (int m = 0; m < 5 && bn < 10; m++) blist[bn++] = p + m * 8; }
        else if (sz == 8)  { if (bn < 10) blist[bn++] = p; }
    }
    for (int i = 0; i < 10; i++) { P.W[i] = wlist[i]; P.B[i] = blist[i]; }

    // 1) pack weights into device staging, 2) D2D copy staging -> __constant__
    //    using REAL device addresses (cudaGetSymbolAddress — the R14 bug was
    //    passing the __device__ shadow symbol as a pointer), 3) main kernel.
    // All graph-capturable: kernel node, memcpy node (D2D), kernel node.
    pack_kernel<<<1, 192>>>(P);
    void* dst = nullptr;
    void* src = nullptr;
    cudaGetSymbolAddress(&dst, cAll);
    cudaGetSymbolAddress(&src, g_pack);
    cudaMemcpyAsync(dst, src, sizeof(ulonglong2) * 180, cudaMemcpyDeviceToDevice, 0);

    int q = batch >> 2;
    int tail = batch - (q << 2);
    int work = q > tail ? q : tail;
    if (work < 1) work = 1;
    int threads = 256;
    int blocks = (work + threads - 1) / threads;
    affine_coupling_kernel<<<blocks, threads>>>((const ulonglong2*)z, (ulonglong2*)d_out, batch);
}